// round 13
// baseline (speedup 1.0000x reference)
#include <cuda_runtime.h>
#include <cuda_fp16.h>
#include <cstdint>

// ---------------------------------------------------------------------------
// Linear SSM as truncated causal conv: y[t] = sum_{d<112} K_d x[t-d], K_0+=D.
// Stage 1: ONE persistent kernel (288 CTAs, software grid barrier) runs the
//          whole GEMM DAG (round-10 dependency-safe phase schedule) with the
//          tap-bank GEMM split z=2 (G8) + fp16 combine/convert (G9).
// Stage 2: mma.sync m16n8k16 fp16 conv; TM=256 per CTA, each warp 32t x 64o,
//          ldmatrix.x4 operands, K taps via cp.async.bulk 4-stage ring.
// ---------------------------------------------------------------------------

#define SEQ   4096
#define BATCH 16
#define DIN   64
#define NST   512
#define DMAX  112
#define TM    256
#define VW    448

#define XSTRH 72
#define KSTRH 72
#define TAPH  4608
#define TAPB  9216
#define NSTG  4

#define SM_X    0
#define SM_K    52992
#define SM_BAR  89856
#define SM_TOTAL 89920

#define NCTA  288

// fp32 scratch
#define OFF_P2   0
#define OFF_P4   262144
#define OFF_P8   524288
#define OFF_P16  786432
#define OFF_P32  1048576
#define OFF_P64  1310720
#define OFF_W    1572864
#define OFF_V    2097152
#define OFF_S0   2326528
#define OFF_S1   3375104
#define SCRATCH_FLOATS 4423680
__device__ float g_scratch[SCRATCH_FLOATS];

// fp16 tap bank: g_K[d*TAPH + o*KSTRH + i]
__device__ __half g_K[DMAX * TAPH];

// grid barrier state
__device__ unsigned int g_arrive;
__device__ volatile unsigned int g_epoch;

// ---------------- PTX helpers ----------------
__device__ __forceinline__ uint32_t smem_u32(const void* p) {
    uint32_t a;
    asm("{ .reg .u64 t; cvta.to.shared.u64 t, %1; cvt.u32.u64 %0, t; }"
        : "=r"(a) : "l"(p));
    return a;
}
#define MBAR_INIT(addr, cnt) \
    asm volatile("mbarrier.init.shared.b64 [%0], %1;" :: "r"(addr), "r"(cnt) : "memory")
#define MBAR_EXPECT_TX(addr, bytes) \
    asm volatile("mbarrier.arrive.expect_tx.shared.b64 _, [%0], %1;" :: "r"(addr), "r"(bytes) : "memory")
#define MBAR_ARRIVE(addr) \
    asm volatile("mbarrier.arrive.release.cta.shared.b64 _, [%0];" :: "r"(addr) : "memory")
#define MBAR_WAIT(addr, par) do { \
    uint32_t _m = (addr), _p = (par), _d; \
    asm volatile("{\n\t.reg .pred p;\n\t" \
        "mbarrier.try_wait.parity.acquire.cta.shared::cta.b64 p, [%1], %2;\n\t" \
        "selp.b32 %0, 1, 0, p;\n\t}" : "=r"(_d) : "r"(_m), "r"(_p) : "memory"); \
    if (!_d) { \
        asm volatile("{\n\t.reg .pred P1;\n\t" \
            "WL_%=:\n\t" \
            "mbarrier.try_wait.parity.acquire.cta.shared::cta.b64 P1, [%0], %1, 0x989680;\n\t" \
            "@P1 bra.uni WD_%=;\n\t" \
            "bra.uni WL_%=;\n\t" \
            "WD_%=:\n\t}" :: "r"(_m), "r"(_p) : "memory"); \
    } \
} while (0)
__device__ __forceinline__ void bulk_g2s(uint32_t dst, const void* src,
                                         uint32_t bytes, uint32_t mbar) {
    asm volatile("cp.async.bulk.shared::cta.global.mbarrier::complete_tx::bytes "
        "[%0], [%1], %2, [%3];" :: "r"(dst), "l"(src), "r"(bytes), "r"(mbar) : "memory");
}
__device__ __forceinline__ void mma_f16(float* c, uint32_t a0, uint32_t a1,
                                        uint32_t a2, uint32_t a3,
                                        uint32_t b0, uint32_t b1) {
    asm volatile("mma.sync.aligned.m16n8k16.row.col.f32.f16.f16.f32 "
        "{%0,%1,%2,%3}, {%4,%5,%6,%7}, {%8,%9}, {%0,%1,%2,%3};"
        : "+f"(c[0]), "+f"(c[1]), "+f"(c[2]), "+f"(c[3])
        : "r"(a0), "r"(a1), "r"(a2), "r"(a3), "r"(b0), "r"(b1));
}
#define LDSM4(r0, r1, r2, r3, addr) \
    asm volatile("ldmatrix.sync.aligned.m8n8.x4.shared.b16 {%0,%1,%2,%3}, [%4];" \
        : "=r"(r0), "=r"(r1), "=r"(r2), "=r"(r3) : "r"(addr))
__device__ __forceinline__ uint32_t pack_h2(float a, float b) {
    __half2 t;
    t.x = __float2half_rn(a);
    t.y = __float2half_rn(b);
    return *(uint32_t*)&t;
}

// ---------------------------------------------------------------------------
// grid barrier (sense-reversing epoch; deterministic)
// ---------------------------------------------------------------------------
__device__ __noinline__ void gbar() {
    __syncthreads();
    if (threadIdx.x == 0) {
        __threadfence();
        unsigned int e = g_epoch;
        if (atomicAdd(&g_arrive, 1u) == NCTA - 1u) {
            g_arrive = 0u;
            __threadfence();
            atomicAdd((unsigned int*)&g_epoch, 1u);
        } else {
            while (g_epoch == e) __nanosleep(32);
        }
        __threadfence();
    }
    __syncthreads();
}

// ---------------------------------------------------------------------------
// 64x64 fp32 GEMM tile over K range [koff, koff+Kc), global-load prefetch.
// ---------------------------------------------------------------------------
__device__ __noinline__ void tileGemm(
    const float* __restrict__ A, const float* __restrict__ B,
    float* __restrict__ out, int ldo, int m0, int n0, int Kc, int koff,
    int lda, int ldb, float (*As)[68], float (*Bs)[68])
{
    const int tid = threadIdx.x;
    const int tn = tid & 15, tm = tid >> 4;
    const int la_m = (tid * 4) >> 4;
    const int la_k = (tid * 4) & 15;
    const int lb_k = (tid * 4) >> 6;
    const int lb_n = (tid * 4) & 63;
    float acc[4][4] = {};

    const float* ap = A + (size_t)(m0 + la_m) * lda + (koff + la_k);
    const float* bp = B + (size_t)(koff + lb_k) * ldb + (n0 + lb_n);
    float4 av = *(const float4*)ap;
    float4 bv = *(const float4*)bp;

    for (int k0 = koff; k0 < koff + Kc; k0 += 16) {
        As[la_k + 0][la_m] = av.x; As[la_k + 1][la_m] = av.y;
        As[la_k + 2][la_m] = av.z; As[la_k + 3][la_m] = av.w;
        *(float4*)&Bs[lb_k][lb_n] = bv;
        __syncthreads();
        if (k0 + 16 < koff + Kc) {
            ap += 16; bp += (size_t)16 * ldb;
            av = *(const float4*)ap;
            bv = *(const float4*)bp;
        }
        #pragma unroll
        for (int kk = 0; kk < 16; kk++) {
            float4 a = *(const float4*)&As[kk][tm * 4];
            float4 b = *(const float4*)&Bs[kk][tn * 4];
            acc[0][0] += a.x * b.x; acc[0][1] += a.x * b.y; acc[0][2] += a.x * b.z; acc[0][3] += a.x * b.w;
            acc[1][0] += a.y * b.x; acc[1][1] += a.y * b.y; acc[1][2] += a.y * b.z; acc[1][3] += a.y * b.w;
            acc[2][0] += a.z * b.x; acc[2][1] += a.z * b.y; acc[2][2] += a.z * b.z; acc[2][3] += a.z * b.w;
            acc[3][0] += a.w * b.x; acc[3][1] += a.w * b.y; acc[3][2] += a.w * b.z; acc[3][3] += a.w * b.w;
        }
        __syncthreads();
    }
    #pragma unroll
    for (int r = 0; r < 4; r++) {
        float4 o = make_float4(acc[r][0], acc[r][1], acc[r][2], acc[r][3]);
        *(float4*)(out + (size_t)(m0 + tm * 4 + r) * ldo + (n0 + tn * 4)) = o;
    }
}

// ---------------------------------------------------------------------------
// fixed z-order slab reduction
// ---------------------------------------------------------------------------
__device__ __noinline__ void redAdd(
    const float* __restrict__ slab, float* __restrict__ dst,
    int ldd, int N, size_t zstride, int Z, int f4base, int f4cnt)
{
    const int fpr = N >> 2;
    for (int i = f4base + threadIdx.x; i < f4base + f4cnt; i += 256) {
        int r = i / fpr, c4 = (i - r * fpr) * 4;
        const float* sp = slab + (size_t)r * N + c4;
        float sx = 0.f, sy = 0.f, sz = 0.f, sw = 0.f;
        for (int z = 0; z < Z; z++) {
            float4 t = *(const float4*)(sp + zstride * z);
            sx += t.x; sy += t.y; sz += t.z; sw += t.w;
        }
        *(float4*)(dst + (size_t)r * ldd + c4) = make_float4(sx, sy, sz, sw);
    }
}

// ---------------------------------------------------------------------------
// kconv: K_d = half0 + half1 (+D for d==0) -> fp16 bank g_K[d][o][i].
// Slabs: S0 + (2d)*4096 and S0 + (2d+1)*4096, each [o][i] dense 64x64.
// ---------------------------------------------------------------------------
__device__ __noinline__ void kconv(int d, const float* __restrict__ Dm)
{
    const float* h0 = g_scratch + OFF_S0 + (size_t)(2 * d) * 4096;
    const float* h1 = h0 + 4096;
    __half* out = g_K + (size_t)d * TAPH;
    const int tid = threadIdx.x;
    #pragma unroll
    for (int v = 0; v < 4; v++) {
        int i4 = tid + v * 256;            // 0..1023 float4 slots
        int o = i4 >> 4, c4 = (i4 & 15) * 4;
        float4 a = *(const float4*)(h0 + o * 64 + c4);
        float4 b = *(const float4*)(h1 + o * 64 + c4);
        float vx = a.x + b.x, vy = a.y + b.y, vz = a.z + b.z, vw = a.w + b.w;
        if (d == 0) {
            float4 dv = *(const float4*)(Dm + o * DIN + c4);
            vx += dv.x; vy += dv.y; vz += dv.z; vw += dv.w;
        }
        uint2 h;
        h.x = pack_h2(vx, vy);
        h.y = pack_h2(vz, vw);
        *(uint2*)(out + o * KSTRH + c4) = h;
    }
}

// ---------------------------------------------------------------------------
// Persistent stage-1 kernel (dependency-safe round-10 schedule + kasm split)
// ---------------------------------------------------------------------------
__global__ __launch_bounds__(256, 2) void stage1(const float* __restrict__ A,
                                                 const float* __restrict__ Dm)
{
    __shared__ float As[16][68];
    __shared__ float Bs[16][68];
    float* S   = g_scratch;
    float* P2  = S + OFF_P2;  float* P4  = S + OFF_P4;
    float* P8  = S + OFF_P8;  float* P16 = S + OFF_P16;
    float* P32 = S + OFF_P32; float* P64 = S + OFF_P64;
    float* W   = S + OFF_W;   float* V   = S + OFF_V;
    float* S0  = S + OFF_S0;  float* S1  = S + OFF_S1;
    const int bid = blockIdx.x;

    // G1: P2 = A*A (z=4, 256 CTA) || W1 = C*A (z=4, 32 CTA)
    if (bid < 256) {
        int t = bid & 63, z = bid >> 6;
        tileGemm(A, A, S0 + (size_t)z * 262144, 512, (t >> 3) * 64, (t & 7) * 64,
                 128, z * 128, 512, 512, As, Bs);
    } else {
        int t = bid - 256, ti = t & 7, z = t >> 3;
        tileGemm(W, A, S1 + (size_t)z * 32768, 512, 0, ti * 64,
                 128, z * 128, 512, 512, As, Bs);
    }
    gbar();
    if (bid < 256) redAdd(S0, P2, 512, 512, 262144, 4, bid * 256, 256);
    else           redAdd(S1, W + (size_t)64 * 512, 512, 512, 32768, 4, (bid - 256) * 256, 256);
    gbar();

    // G2: P4 = P2^2 (z=4, 256 CTA) || W2 = W[0:128)*P2 (z=2, 32 CTA)
    // (W2 depends only on W[0:128) and P2, both ready after R1)
    if (bid < 256) {
        int t = bid & 63, z = bid >> 6;
        tileGemm(P2, P2, S0 + (size_t)z * 262144, 512, (t >> 3) * 64, (t & 7) * 64,
                 128, z * 128, 512, 512, As, Bs);
    } else {
        int t = bid - 256, tile = t & 15, z = t >> 4;
        tileGemm(W, P2, S1 + (size_t)z * 65536, 512, (tile >> 3) * 64, (tile & 7) * 64,
                 256, z * 256, 512, 512, As, Bs);
    }
    gbar();
    if (bid < 256) redAdd(S0, P4, 512, 512, 262144, 4, bid * 256, 256);
    else           redAdd(S1, W + (size_t)128 * 512, 512, 512, 65536, 2, (bid - 256) * 512, 512);
    gbar();

    // G3: P8 = P4^2 (z=2, 128 CTA) || W3 = W[0:256)*P4 (z=4, 128 CTA)
    // (W3 reads W rows [0,256) — complete after R2)
    if (bid < 128) {
        int t = bid & 63, z = bid >> 6;
        tileGemm(P4, P4, S0 + (size_t)z * 262144, 512, (t >> 3) * 64, (t & 7) * 64,
                 256, z * 256, 512, 512, As, Bs);
    } else if (bid < 256) {
        int t = bid - 128, tile = t & 31, z = t >> 5;
        tileGemm(W, P4, S1 + (size_t)z * 131072, 512, (tile >> 3) * 64, (tile & 7) * 64,
                 128, z * 128, 512, 512, As, Bs);
    }
    gbar();
    if (bid < 128)      redAdd(S0, P8, 512, 512, 262144, 2, bid * 512, 512);
    else if (bid < 256) redAdd(S1, W + (size_t)256 * 512, 512, 512, 131072, 4, (bid - 128) * 256, 256);
    gbar();

    // G4: P16 = P8^2 (z=2, 128 CTA) || W4 = W[0:512)*P8 (z=2, 128 CTA)
    if (bid < 128) {
        int t = bid & 63, z = bid >> 6;
        tileGemm(P8, P8, S0 + (size_t)z * 262144, 512, (t >> 3) * 64, (t & 7) * 64,
                 256, z * 256, 512, 512, As, Bs);
    } else if (bid < 256) {
        int t = bid - 128, tile = t & 63, z = t >> 6;
        tileGemm(W, P8, S1 + (size_t)z * 262144, 512, (tile >> 3) * 64, (tile & 7) * 64,
                 256, z * 256, 512, 512, As, Bs);
    }
    gbar();
    if (bid < 128)      redAdd(S0, P16, 512, 512, 262144, 2, bid * 512, 512);
    else if (bid < 256) redAdd(S1, W + (size_t)512 * 512, 512, 512, 262144, 2, (bid - 128) * 512, 512);
    gbar();

    // G5: P32 = P16^2 (z=4, 256 CTA) || V1 = P16*V0 (z=4, 32 CTA)
    if (bid < 256) {
        int t = bid & 63, z = bid >> 6;
        tileGemm(P16, P16, S0 + (size_t)z * 262144, 512, (t >> 3) * 64, (t & 7) * 64,
                 128, z * 128, 512, 512, As, Bs);
    } else {
        int t = bid - 256, ti = t & 7, z = t >> 3;
        tileGemm(P16, V, S1 + (size_t)z * 32768, 64, ti * 64, 0,
                 128, z * 128, 512, VW, As, Bs);
    }
    gbar();
    if (bid < 256) redAdd(S0, P32, 512, 512, 262144, 4, bid * 256, 256);
    else           redAdd(S1, V + 64, VW, 64, 32768, 4, (bid - 256) * 256, 256);
    gbar();

    // G6: P64 = P32^2 (z=4, 256 CTA) || V23 = P32*V[0:128) (z=2, 32 CTA)
    if (bid < 256) {
        int t = bid & 63, z = bid >> 6;
        tileGemm(P32, P32, S0 + (size_t)z * 262144, 512, (t >> 3) * 64, (t & 7) * 64,
                 128, z * 128, 512, 512, As, Bs);
    } else {
        int t = bid - 256, tile = t & 15, z = t >> 4;
        tileGemm(P32, V, S1 + (size_t)z * 65536, 128, (tile >> 1) * 64, (tile & 1) * 64,
                 256, z * 256, 512, VW, As, Bs);
    }
    gbar();
    if (bid < 256) redAdd(S0, P64, 512, 512, 262144, 4, bid * 256, 256);
    else           redAdd(S1, V + 128, VW, 128, 65536, 2, (bid - 256) * 512, 512);
    gbar();

    // G7: V456 = P64*V[0:192) (z=8, 192 CTA)
    if (bid < 192) {
        int z = bid / 24, tile = bid % 24;
        tileGemm(P64, V, S0 + (size_t)z * 98304, 192, (tile / 3) * 64, (tile % 3) * 64,
                 64, z * 64, 512, VW, As, Bs);
    }
    gbar();
    if (bid < 192) redAdd(S0, V + 256, VW, 192, 98304, 8, bid * 128, 128);
    gbar();

    // G8: tap bank partials, z=2 (224 CTAs, 16ch each):
    //     CTA 2d+h computes W_{d&15} * V_{d>>4} over K half h into S0+bid*4096
    if (bid < 224) {
        int d = bid >> 1, half = bid & 1;
        int d1 = d & 15, j = d >> 4;
        tileGemm(W + (size_t)d1 * 64 * NST, V + j * 64,
                 S0 + (size_t)bid * 4096, 64, 0, 0,
                 256, half * 256, NST, VW, As, Bs);
    }
    gbar();

    // G9: combine halves (+D), convert to fp16 tap bank
    if (bid < DMAX) kconv(bid, Dm);
}

// ---------------------------------------------------------------------------
// fp16 mma.sync conv: TM=256, 8 warps x (32t x 64o), ldmatrix.x4 operands.
// (unchanged - validated at ~139us, tensor 70.6%)
// ---------------------------------------------------------------------------
__global__ __launch_bounds__(256, 2) void conv_tc(const float* __restrict__ x,
                                                  float* __restrict__ y)
{
    extern __shared__ char sm[];
    __half* Xs = (__half*)(sm + SM_X);
    const uint32_t sb = smem_u32(sm);
    const uint32_t barF = sb + SM_BAR;
    const uint32_t barE = sb + SM_BAR + 32;
    const int tid = threadIdx.x;
    const int wid = tid >> 5, lane = tid & 31;
    const int gid = lane >> 2, tig = lane & 3;
    const int b = blockIdx.y;
    const int t0 = blockIdx.x * TM;

    if (tid == 0) {
        #pragma unroll
        for (int s = 0; s < NSTG; s++) {
            MBAR_INIT(barF + s * 8, 1);
            MBAR_INIT(barE + s * 8, 8);
        }
    }
    __syncthreads();

    if (tid == 0) {
        #pragma unroll
        for (int s = 0; s < NSTG; s++) {
            MBAR_EXPECT_TX(barF + s * 8, TAPB);
            bulk_g2s(sb + SM_K + s * TAPB, g_K + (size_t)s * TAPH, TAPB, barF + s * 8);
        }
    }

    for (int u = tid; u < TM + DMAX - 1; u += 256) {
        int tg = t0 - (DMAX - 1) + u;
        uint32_t* dst = (uint32_t*)(Xs + u * XSTRH);
        if (tg >= 0) {
            const float4* src = (const float4*)(x + ((size_t)b * SEQ + tg) * DIN);
            #pragma unroll
            for (int c = 0; c < 16; c += 2) {
                float4 v0 = src[c], v1 = src[c + 1];
                uint4 h;
                h.x = pack_h2(v0.x, v0.y); h.y = pack_h2(v0.z, v0.w);
                h.z = pack_h2(v1.x, v1.y); h.w = pack_h2(v1.z, v1.w);
                *(uint4*)(dst + c * 2) = h;
            }
        } else {
            #pragma unroll
            for (int c = 0; c < 8; c++)
                *(uint4*)(dst + c * 4) = make_uint4(0, 0, 0, 0);
        }
    }
    __syncthreads();

    float acc[16][4];
    #pragma unroll
    for (int nf = 0; nf < 16; nf++) {
        acc[nf][0] = 0.f; acc[nf][1] = 0.f; acc[nf][2] = 0.f; acc[nf][3] = 0.f;
    }

    const uint32_t invA = (uint32_t)(wid * 32 + (lane & 15)) * 144u
                        + (uint32_t)(lane >> 4) * 16u;
    const uint32_t invB = (uint32_t)((lane & 7) + ((lane >> 4) << 3)) * 144u
                        + (uint32_t)((lane >> 3) & 1) * 16u;

    for (int d = 0; d < DMAX; d++) {
        const int s = d & 3;
        const uint32_t par = (d >> 2) & 1;
        MBAR_WAIT(barF + s * 8, par);

        const uint32_t aBase = sb + SM_X + invA + (uint32_t)(DMAX - 1 - d) * 144u;
        const uint32_t bBase = sb + SM_K + (uint32_t)s * TAPB + invB;

        #pragma unroll
        for (int kc = 0; kc < 4; kc++) {
            uint32_t a0, a1, a2, a3, a4, a5, a6, a7;
            LDSM4(a0, a1, a2, a3, aBase + kc * 32);
            LDSM4(a4, a5, a6, a7, aBase + 2304 + kc * 32);
            #pragma unroll
            for (int nfp = 0; nfp < 4; nfp++) {
                uint32_t b0, b1, b2, b3;
                LDSM4(b0, b1, b2, b3, bBase + nfp * 2304 + kc * 32);
                mma_f16(acc[2 * nfp],         a0, a1, a2, a3, b0, b1);
                mma_f16(acc[2 * nfp + 1],     a0, a1, a2, a3, b2, b3);
                mma_f16(acc[8 + 2 * nfp],     a4, a5, a6, a7, b0, b1);
                mma_f16(acc[8 + 2 * nfp + 1], a4, a5, a6, a7, b2, b3);
            }
        }

        if (lane == 0) MBAR_ARRIVE(barE + s * 8);
        if (tid == 0 && d + NSTG < DMAX) {
            MBAR_WAIT(barE + s * 8, par);
            MBAR_EXPECT_TX(barF + s * 8, TAPB);
            bulk_g2s(sb + SM_K + s * TAPB, g_K + (size_t)(d + NSTG) * TAPH, TAPB,
                     barF + s * 8);
        }
    }

    const int r0 = t0 + wid * 32 + gid;
    #pragma unroll
    for (int nf = 0; nf < 8; nf++) {
        int col = nf * 8 + 2 * tig;
        *(float2*)(y + ((size_t)b * SEQ + r0) * DIN + col) =
            make_float2(acc[nf][0], acc[nf][1]);
        *(float2*)(y + ((size_t)b * SEQ + r0 + 8) * DIN + col) =
            make_float2(acc[nf][2], acc[nf][3]);
        *(float2*)(y + ((size_t)b * SEQ + r0 + 16) * DIN + col) =
            make_float2(acc[8 + nf][0], acc[8 + nf][1]);
        *(float2*)(y + ((size_t)b * SEQ + r0 + 24) * DIN + col) =
            make_float2(acc[8 + nf][2], acc[8 + nf][3]);
    }
}

// ---------------------------------------------------------------------------
extern "C" void kernel_launch(void* const* d_in, const int* in_sizes, int n_in,
                              void* d_out, int out_size)
{
    const float* x  = (const float*)d_in[0];
    const float* A  = (const float*)d_in[1];
    const float* Bm = (const float*)d_in[2];
    const float* Cm = (const float*)d_in[3];
    const float* Dm = (const float*)d_in[4];
    float* y = (float*)d_out;

    float* s = nullptr;
    cudaGetSymbolAddress((void**)&s, g_scratch);
    float* W = s + OFF_W;
    float* V = s + OFF_V;

    cudaFuncSetAttribute(conv_tc, cudaFuncAttributeMaxDynamicSharedMemorySize, SM_TOTAL);

    // seed W row-block 0 <- C ; V col-block 0 <- B
    cudaMemcpyAsync(W, Cm, (size_t)64 * NST * sizeof(float), cudaMemcpyDeviceToDevice);
    cudaMemcpy2DAsync(V, VW * sizeof(float), Bm, 64 * sizeof(float),
                      64 * sizeof(float), NST, cudaMemcpyDeviceToDevice);

    // whole stage 1 in one persistent launch
    stage1<<<NCTA, 256>>>(A, Dm);

    // tensor-core convolution (TM=256, warp tile 32t x 64o)
    conv_tc<<<dim3(SEQ / TM, BATCH), 256, SM_TOTAL>>>(x, y);
}

// round 14
// speedup vs baseline: 1.0507x; 1.0507x over previous
#include <cuda_runtime.h>
#include <cuda_fp16.h>
#include <cstdint>

// ---------------------------------------------------------------------------
// Linear SSM as truncated causal conv: y[t] = sum_{d<104} K_d x[t-d], K_0+=D.
// Stage 1: ONE persistent kernel (288 CTAs, grid barrier). P-chain only to
//          P32 (V4..V6 from P32); tap-bank GEMMs (z=8) pipelined alongside
//          the V phases, with per-group kconv (Z=8 fixed-order) one phase
//          behind through 4 rotating slab regions. 85 max-chunks, 18 bars.
// Stage 2: mma.sync m16n8k16 fp16 conv; TM=256, warp tile 32t x 64o,
//          ldmatrix.x4, K taps via cp.async.bulk 4-stage ring. DMAX=104
//          (trunc 4.8e-4 + fp16 2.9e-4 -> ~5.6e-4 total, under 1e-3).
// ---------------------------------------------------------------------------

#define SEQ   4096
#define BATCH 16
#define DIN   64
#define NST   512
#define DMAX  104
#define TM    256
#define VW    448

#define XSTRH 72
#define KSTRH 72
#define TAPH  4608
#define TAPB  9216
#define NSTG  4

#define SM_X    0
#define SM_K    51840        // 360 rows * 144B
#define SM_BAR  88704        // 51840 + 4*9216
#define SM_TOTAL 88832

#define NCTA  288

// fp32 scratch
#define OFF_P2   0
#define OFF_P4   262144
#define OFF_P8   524288
#define OFF_P16  786432
#define OFF_P32  1048576
#define OFF_W    1572864
#define OFF_V    2097152
#define OFF_S0   2326528
#define OFF_S1   3375104
#define SCRATCH_FLOATS 4423680
__device__ float g_scratch[SCRATCH_FLOATS];

// fp16 tap bank: g_K[d*TAPH + o*KSTRH + i]
__device__ __half g_K[DMAX * TAPH];

// grid barrier state
__device__ unsigned int g_arrive;
__device__ volatile unsigned int g_epoch;

// ---------------- PTX helpers ----------------
__device__ __forceinline__ uint32_t smem_u32(const void* p) {
    uint32_t a;
    asm("{ .reg .u64 t; cvta.to.shared.u64 t, %1; cvt.u32.u64 %0, t; }"
        : "=r"(a) : "l"(p));
    return a;
}
#define MBAR_INIT(addr, cnt) \
    asm volatile("mbarrier.init.shared.b64 [%0], %1;" :: "r"(addr), "r"(cnt) : "memory")
#define MBAR_EXPECT_TX(addr, bytes) \
    asm volatile("mbarrier.arrive.expect_tx.shared.b64 _, [%0], %1;" :: "r"(addr), "r"(bytes) : "memory")
#define MBAR_ARRIVE(addr) \
    asm volatile("mbarrier.arrive.release.cta.shared.b64 _, [%0];" :: "r"(addr) : "memory")
#define MBAR_WAIT(addr, par) do { \
    uint32_t _m = (addr), _p = (par), _d; \
    asm volatile("{\n\t.reg .pred p;\n\t" \
        "mbarrier.try_wait.parity.acquire.cta.shared::cta.b64 p, [%1], %2;\n\t" \
        "selp.b32 %0, 1, 0, p;\n\t}" : "=r"(_d) : "r"(_m), "r"(_p) : "memory"); \
    if (!_d) { \
        asm volatile("{\n\t.reg .pred P1;\n\t" \
            "WL_%=:\n\t" \
            "mbarrier.try_wait.parity.acquire.cta.shared::cta.b64 P1, [%0], %1, 0x989680;\n\t" \
            "@P1 bra.uni WD_%=;\n\t" \
            "bra.uni WL_%=;\n\t" \
            "WD_%=:\n\t}" :: "r"(_m), "r"(_p) : "memory"); \
    } \
} while (0)
__device__ __forceinline__ void bulk_g2s(uint32_t dst, const void* src,
                                         uint32_t bytes, uint32_t mbar) {
    asm volatile("cp.async.bulk.shared::cta.global.mbarrier::complete_tx::bytes "
        "[%0], [%1], %2, [%3];" :: "r"(dst), "l"(src), "r"(bytes), "r"(mbar) : "memory");
}
__device__ __forceinline__ void mma_f16(float* c, uint32_t a0, uint32_t a1,
                                        uint32_t a2, uint32_t a3,
                                        uint32_t b0, uint32_t b1) {
    asm volatile("mma.sync.aligned.m16n8k16.row.col.f32.f16.f16.f32 "
        "{%0,%1,%2,%3}, {%4,%5,%6,%7}, {%8,%9}, {%0,%1,%2,%3};"
        : "+f"(c[0]), "+f"(c[1]), "+f"(c[2]), "+f"(c[3])
        : "r"(a0), "r"(a1), "r"(a2), "r"(a3), "r"(b0), "r"(b1));
}
#define LDSM4(r0, r1, r2, r3, addr) \
    asm volatile("ldmatrix.sync.aligned.m8n8.x4.shared.b16 {%0,%1,%2,%3}, [%4];" \
        : "=r"(r0), "=r"(r1), "=r"(r2), "=r"(r3) : "r"(addr))
__device__ __forceinline__ uint32_t pack_h2(float a, float b) {
    __half2 t;
    t.x = __float2half_rn(a);
    t.y = __float2half_rn(b);
    return *(uint32_t*)&t;
}

// ---------------------------------------------------------------------------
// grid barrier (sense-reversing epoch; deterministic)
// ---------------------------------------------------------------------------
__device__ __noinline__ void gbar() {
    __syncthreads();
    if (threadIdx.x == 0) {
        __threadfence();
        unsigned int e = g_epoch;
        if (atomicAdd(&g_arrive, 1u) == NCTA - 1u) {
            g_arrive = 0u;
            __threadfence();
            atomicAdd((unsigned int*)&g_epoch, 1u);
        } else {
            while (g_epoch == e) __nanosleep(32);
        }
        __threadfence();
    }
    __syncthreads();
}

// ---------------------------------------------------------------------------
// 64x64 fp32 GEMM tile over K range [koff, koff+Kc), global-load prefetch.
// ---------------------------------------------------------------------------
__device__ __noinline__ void tileGemm(
    const float* __restrict__ A, const float* __restrict__ B,
    float* __restrict__ out, int ldo, int m0, int n0, int Kc, int koff,
    int lda, int ldb, float (*As)[68], float (*Bs)[68])
{
    const int tid = threadIdx.x;
    const int tn = tid & 15, tm = tid >> 4;
    const int la_m = (tid * 4) >> 4;
    const int la_k = (tid * 4) & 15;
    const int lb_k = (tid * 4) >> 6;
    const int lb_n = (tid * 4) & 63;
    float acc[4][4] = {};

    const float* ap = A + (size_t)(m0 + la_m) * lda + (koff + la_k);
    const float* bp = B + (size_t)(koff + lb_k) * ldb + (n0 + lb_n);
    float4 av = *(const float4*)ap;
    float4 bv = *(const float4*)bp;

    for (int k0 = koff; k0 < koff + Kc; k0 += 16) {
        As[la_k + 0][la_m] = av.x; As[la_k + 1][la_m] = av.y;
        As[la_k + 2][la_m] = av.z; As[la_k + 3][la_m] = av.w;
        *(float4*)&Bs[lb_k][lb_n] = bv;
        __syncthreads();
        if (k0 + 16 < koff + Kc) {
            ap += 16; bp += (size_t)16 * ldb;
            av = *(const float4*)ap;
            bv = *(const float4*)bp;
        }
        #pragma unroll
        for (int kk = 0; kk < 16; kk++) {
            float4 a = *(const float4*)&As[kk][tm * 4];
            float4 b = *(const float4*)&Bs[kk][tn * 4];
            acc[0][0] += a.x * b.x; acc[0][1] += a.x * b.y; acc[0][2] += a.x * b.z; acc[0][3] += a.x * b.w;
            acc[1][0] += a.y * b.x; acc[1][1] += a.y * b.y; acc[1][2] += a.y * b.z; acc[1][3] += a.y * b.w;
            acc[2][0] += a.z * b.x; acc[2][1] += a.z * b.y; acc[2][2] += a.z * b.z; acc[2][3] += a.z * b.w;
            acc[3][0] += a.w * b.x; acc[3][1] += a.w * b.y; acc[3][2] += a.w * b.z; acc[3][3] += a.w * b.w;
        }
        __syncthreads();
    }
    #pragma unroll
    for (int r = 0; r < 4; r++) {
        float4 o = make_float4(acc[r][0], acc[r][1], acc[r][2], acc[r][3]);
        *(float4*)(out + (size_t)(m0 + tm * 4 + r) * ldo + (n0 + tn * 4)) = o;
    }
}

// ---------------------------------------------------------------------------
// fixed z-order slab reduction
// ---------------------------------------------------------------------------
__device__ __noinline__ void redAdd(
    const float* __restrict__ slab, float* __restrict__ dst,
    int ldd, int N, size_t zstride, int Z, int f4base, int f4cnt)
{
    const int fpr = N >> 2;
    for (int i = f4base + threadIdx.x; i < f4base + f4cnt; i += 256) {
        int r = i / fpr, c4 = (i - r * fpr) * 4;
        const float* sp = slab + (size_t)r * N + c4;
        float sx = 0.f, sy = 0.f, sz = 0.f, sw = 0.f;
        for (int z = 0; z < Z; z++) {
            float4 t = *(const float4*)(sp + zstride * z);
            sx += t.x; sy += t.y; sz += t.z; sw += t.w;
        }
        *(float4*)(dst + (size_t)r * ldd + c4) = make_float4(sx, sy, sz, sw);
    }
}

// ---------------------------------------------------------------------------
// kconv8: K_d = sum of 8 partial slabs (+D for d==0) -> fp16 g_K[d][o][i].
// base -> this tap's 8 slabs at base + z*4096 (dense 64x64 [o][i]).
// ---------------------------------------------------------------------------
__device__ __noinline__ void kconv8(int d, const float* __restrict__ base,
                                    const float* __restrict__ Dm)
{
    __half* out = g_K + (size_t)d * TAPH;
    const int tid = threadIdx.x;
    #pragma unroll
    for (int v = 0; v < 4; v++) {
        int i4 = tid + v * 256;
        int o = i4 >> 4, c4 = (i4 & 15) * 4;
        float sx = 0.f, sy = 0.f, sz = 0.f, sw = 0.f;
        #pragma unroll
        for (int z = 0; z < 8; z++) {
            float4 t = *(const float4*)(base + z * 4096 + o * 64 + c4);
            sx += t.x; sy += t.y; sz += t.z; sw += t.w;
        }
        if (d == 0) {
            float4 dv = *(const float4*)(Dm + o * DIN + c4);
            sx += dv.x; sy += dv.y; sz += dv.z; sw += dv.w;
        }
        uint2 h;
        h.x = pack_h2(sx, sy);
        h.y = pack_h2(sz, sw);
        *(uint2*)(out + o * KSTRH + c4) = h;
    }
}

// ---------------------------------------------------------------------------
// Persistent stage-1 kernel
// ---------------------------------------------------------------------------
__global__ __launch_bounds__(256, 2) void stage1(const float* __restrict__ A,
                                                 const float* __restrict__ Dm)
{
    __shared__ float As[16][68];
    __shared__ float Bs[16][68];
    float* S   = g_scratch;
    float* P2  = S + OFF_P2;  float* P4  = S + OFF_P4;
    float* P8  = S + OFF_P8;  float* P16 = S + OFF_P16;
    float* P32 = S + OFF_P32;
    float* W   = S + OFF_W;   float* V   = S + OFF_V;
    float* S0  = S + OFF_S0;  float* S1  = S + OFF_S1;
    float* RT0 = S0;          float* RT1 = S0 + 524288;
    float* RT2 = S1;          float* RT3 = S1 + 524288;
    const int bid = blockIdx.x;

    // G1: P2 = A*A (z=4, 256) || W1 = C*A (z=4, 32)           [8ch]
    if (bid < 256) {
        int t = bid & 63, z = bid >> 6;
        tileGemm(A, A, S0 + (size_t)z * 262144, 512, (t >> 3) * 64, (t & 7) * 64,
                 128, z * 128, 512, 512, As, Bs);
    } else {
        int t = bid - 256, ti = t & 7, z = t >> 3;
        tileGemm(W, A, S1 + (size_t)z * 32768, 512, 0, ti * 64,
                 128, z * 128, 512, 512, As, Bs);
    }
    gbar();
    if (bid < 256) redAdd(S0, P2, 512, 512, 262144, 4, bid * 256, 256);
    else           redAdd(S1, W + (size_t)64 * 512, 512, 512, 32768, 4, (bid - 256) * 256, 256);
    gbar();

    // G2: P4 = P2^2 (z=4, 256) || W2 = W[0:128)*P2 (z=2, 32)  [16ch]
    if (bid < 256) {
        int t = bid & 63, z = bid >> 6;
        tileGemm(P2, P2, S0 + (size_t)z * 262144, 512, (t >> 3) * 64, (t & 7) * 64,
                 128, z * 128, 512, 512, As, Bs);
    } else {
        int t = bid - 256, tile = t & 15, z = t >> 4;
        tileGemm(W, P2, S1 + (size_t)z * 65536, 512, (tile >> 3) * 64, (tile & 7) * 64,
                 256, z * 256, 512, 512, As, Bs);
    }
    gbar();
    if (bid < 256) redAdd(S0, P4, 512, 512, 262144, 4, bid * 256, 256);
    else           redAdd(S1, W + (size_t)128 * 512, 512, 512, 65536, 2, (bid - 256) * 512, 512);
    gbar();

    // G3: P8 = P4^2 (z=2, 128) || W3 = W[0:256)*P4 (z=4, 128) [16ch]
    if (bid < 128) {
        int t = bid & 63, z = bid >> 6;
        tileGemm(P4, P4, S0 + (size_t)z * 262144, 512, (t >> 3) * 64, (t & 7) * 64,
                 256, z * 256, 512, 512, As, Bs);
    } else if (bid < 256) {
        int t = bid - 128, tile = t & 31, z = t >> 5;
        tileGemm(W, P4, S1 + (size_t)z * 131072, 512, (tile >> 3) * 64, (tile & 7) * 64,
                 128, z * 128, 512, 512, As, Bs);
    }
    gbar();
    if (bid < 128)      redAdd(S0, P8, 512, 512, 262144, 2, bid * 512, 512);
    else if (bid < 256) redAdd(S1, W + (size_t)256 * 512, 512, 512, 131072, 4, (bid - 128) * 256, 256);
    gbar();

    // G4: P16 = P8^2 (z=2, 128) || W4 = W[0:512)*P8 (z=2, 128) [16ch]
    if (bid < 128) {
        int t = bid & 63, z = bid >> 6;
        tileGemm(P8, P8, S0 + (size_t)z * 262144, 512, (t >> 3) * 64, (t & 7) * 64,
                 256, z * 256, 512, 512, As, Bs);
    } else if (bid < 256) {
        int t = bid - 128, tile = t & 63, z = t >> 6;
        tileGemm(W, P8, S1 + (size_t)z * 262144, 512, (tile >> 3) * 64, (tile & 7) * 64,
                 256, z * 256, 512, 512, As, Bs);
    }
    gbar();
    if (bid < 128)      redAdd(S0, P16, 512, 512, 262144, 2, bid * 512, 512);
    else if (bid < 256) redAdd(S1, W + (size_t)512 * 512, 512, 512, 262144, 2, (bid - 128) * 512, 512);
    gbar();

    // G5: P32 = P16^2 (z=4, 256, S0) || V1 = P16*V0 (z=4, 32, S1) [8ch]
    if (bid < 256) {
        int t = bid & 63, z = bid >> 6;
        tileGemm(P16, P16, S0 + (size_t)z * 262144, 512, (t >> 3) * 64, (t & 7) * 64,
                 128, z * 128, 512, 512, As, Bs);
    } else {
        int t = bid - 256, ti = t & 7, z = t >> 3;
        tileGemm(P16, V, S1 + (size_t)z * 32768, 64, ti * 64, 0,
                 128, z * 128, 512, VW, As, Bs);
    }
    gbar();
    if (bid < 256) redAdd(S0, P32, 512, 512, 262144, 4, bid * 256, 256);
    else           redAdd(S1, V + 64, VW, 64, 32768, 4, (bid - 256) * 256, 256);
    gbar();

    // G6: taps j0 -> RT0 (128, z=8) || V23 = P32*V[0:128) -> RT2 (128, z=8) [4ch]
    if (bid < 128) {
        int tl = bid >> 3, z = bid & 7;   // tap d = tl, B = V0
        tileGemm(W + (size_t)tl * 64 * NST, V,
                 RT0 + (size_t)bid * 4096, 64, 0, 0, 64, z * 64, NST, VW, As, Bs);
    } else if (bid < 256) {
        int t = bid - 128, tile = t >> 3, z = t & 7;
        int mt = tile >> 1, nt = tile & 1;
        tileGemm(P32, V, RT2 + (size_t)z * 65536, 128, mt * 64, nt * 64,
                 64, z * 64, 512, VW, As, Bs);
    }
    gbar();
    if (bid < 128) redAdd(RT2, V + 128, VW, 128, 65536, 8, bid * 128, 128);
    gbar();

    // G7: taps j1 -> RT1 || V45 = P32*V[128:256) -> RT3 || kconv j0 [4ch]
    if (bid < 128) {
        int tl = bid >> 3, z = bid & 7;   // tap d = 16+tl, B = V1
        tileGemm(W + (size_t)tl * 64 * NST, V + 64,
                 RT1 + (size_t)bid * 4096, 64, 0, 0, 64, z * 64, NST, VW, As, Bs);
    } else if (bid < 256) {
        int t = bid - 128, tile = t >> 3, z = t & 7;
        int mt = tile >> 1, nt = tile & 1;
        tileGemm(P32, V + 128, RT3 + (size_t)z * 65536, 128, mt * 64, nt * 64,
                 64, z * 64, 512, VW, As, Bs);
    } else if (bid < 272) {
        int d = bid - 256;                // taps 0..15
        kconv8(d, RT0 + (size_t)d * 32768, Dm);
    }
    gbar();
    if (bid < 128) redAdd(RT3, V + 256, VW, 128, 65536, 8, bid * 128, 128);
    gbar();

    // G8: V6 = P32*V4 -> RT0 (64, z=8) || taps j2 -> RT2 || kconv j1 [4ch]
    if (bid < 64) {
        int mt = bid >> 3, z = bid & 7;
        tileGemm(P32, V + 256, RT0 + (size_t)z * 32768, 64, mt * 64, 0,
                 64, z * 64, 512, VW, As, Bs);
    } else if (bid < 192) {
        int l = bid - 64, tl = l >> 3, z = l & 7;   // tap d = 32+tl, B = V2
        tileGemm(W + (size_t)tl * 64 * NST, V + 128,
                 RT2 + (size_t)l * 4096, 64, 0, 0, 64, z * 64, NST, VW, As, Bs);
    } else if (bid < 208) {
        int lt = bid - 192;               // taps 16..31
        kconv8(16 + lt, RT1 + (size_t)lt * 32768, Dm);
    }
    gbar();
    if (bid < 64) redAdd(RT0, V + 384, VW, 64, 32768, 8, bid * 128, 128);
    gbar();

    // G9: taps j3 -> RT3 || taps j4 -> RT1 || kconv j2  [4ch, 1 bar]
    if (bid < 128) {
        int tl = bid >> 3, z = bid & 7;   // d = 48+tl, B = V3
        tileGemm(W + (size_t)tl * 64 * NST, V + 192,
                 RT3 + (size_t)bid * 4096, 64, 0, 0, 64, z * 64, NST, VW, As, Bs);
    } else if (bid < 256) {
        int l = bid - 128, tl = l >> 3, z = l & 7;  // d = 64+tl, B = V4
        tileGemm(W + (size_t)tl * 64 * NST, V + 256,
                 RT1 + (size_t)l * 4096, 64, 0, 0, 64, z * 64, NST, VW, As, Bs);
    } else if (bid < 272) {
        int lt = bid - 256;               // taps 32..47
        kconv8(32 + lt, RT2 + (size_t)lt * 32768, Dm);
    }
    gbar();

    // G10: taps j5 -> RT0 || taps j6 (8 taps) -> RT2 || kconv j3, j4 [4ch, 1 bar]
    if (bid < 128) {
        int tl = bid >> 3, z = bid & 7;   // d = 80+tl, B = V5
        tileGemm(W + (size_t)tl * 64 * NST, V + 320,
                 RT0 + (size_t)bid * 4096, 64, 0, 0, 64, z * 64, NST, VW, As, Bs);
    } else if (bid < 192) {
        int l = bid - 128, tl = l >> 3, z = l & 7;  // d = 96+tl (tl<8), B = V6
        tileGemm(W + (size_t)tl * 64 * NST, V + 384,
                 RT2 + (size_t)l * 4096, 64, 0, 0, 64, z * 64, NST, VW, As, Bs);
    } else if (bid < 208) {
        int lt = bid - 192;               // taps 48..63
        kconv8(48 + lt, RT3 + (size_t)lt * 32768, Dm);
    } else if (bid < 224) {
        int lt = bid - 208;               // taps 64..79
        kconv8(64 + lt, RT1 + (size_t)lt * 32768, Dm);
    }
    gbar();

    // G11: kconv j5 (16) + j6 (8)
    if (bid < 16)      kconv8(80 + bid, RT0 + (size_t)bid * 32768, Dm);
    else if (bid < 24) kconv8(96 + (bid - 16), RT2 + (size_t)(bid - 16) * 32768, Dm);
}

// ---------------------------------------------------------------------------
// fp16 mma.sync conv: TM=256, 8 warps x (32t x 64o), ldmatrix.x4 operands.
// ---------------------------------------------------------------------------
__global__ __launch_bounds__(256, 2) void conv_tc(const float* __restrict__ x,
                                                  float* __restrict__ y)
{
    extern __shared__ char sm[];
    __half* Xs = (__half*)(sm + SM_X);
    const uint32_t sb = smem_u32(sm);
    const uint32_t barF = sb + SM_BAR;
    const uint32_t barE = sb + SM_BAR + 32;
    const int tid = threadIdx.x;
    const int wid = tid >> 5, lane = tid & 31;
    const int gid = lane >> 2, tig = lane & 3;
    const int b = blockIdx.y;
    const int t0 = blockIdx.x * TM;

    if (tid == 0) {
        #pragma unroll
        for (int s = 0; s < NSTG; s++) {
            MBAR_INIT(barF + s * 8, 1);
            MBAR_INIT(barE + s * 8, 8);
        }
    }
    __syncthreads();

    if (tid == 0) {
        #pragma unroll
        for (int s = 0; s < NSTG; s++) {
            MBAR_EXPECT_TX(barF + s * 8, TAPB);
            bulk_g2s(sb + SM_K + s * TAPB, g_K + (size_t)s * TAPH, TAPB, barF + s * 8);
        }
    }

    for (int u = tid; u < TM + DMAX - 1; u += 256) {
        int tg = t0 - (DMAX - 1) + u;
        uint32_t* dst = (uint32_t*)(Xs + u * XSTRH);
        if (tg >= 0) {
            const float4* src = (const float4*)(x + ((size_t)b * SEQ + tg) * DIN);
            #pragma unroll
            for (int c = 0; c < 16; c += 2) {
                float4 v0 = src[c], v1 = src[c + 1];
                uint4 h;
                h.x = pack_h2(v0.x, v0.y); h.y = pack_h2(v0.z, v0.w);
                h.z = pack_h2(v1.x, v1.y); h.w = pack_h2(v1.z, v1.w);
                *(uint4*)(dst + c * 2) = h;
            }
        } else {
            #pragma unroll
            for (int c = 0; c < 8; c++)
                *(uint4*)(dst + c * 4) = make_uint4(0, 0, 0, 0);
        }
    }
    __syncthreads();

    float acc[16][4];
    #pragma unroll
    for (int nf = 0; nf < 16; nf++) {
        acc[nf][0] = 0.f; acc[nf][1] = 0.f; acc[nf][2] = 0.f; acc[nf][3] = 0.f;
    }

    const uint32_t invA = (uint32_t)(wid * 32 + (lane & 15)) * 144u
                        + (uint32_t)(lane >> 4) * 16u;
    const uint32_t invB = (uint32_t)((lane & 7) + ((lane >> 4) << 3)) * 144u
                        + (uint32_t)((lane >> 3) & 1) * 16u;

    for (int d = 0; d < DMAX; d++) {
        const int s = d & 3;
        const uint32_t par = (d >> 2) & 1;
        MBAR_WAIT(barF + s * 8, par);

        const uint32_t aBase = sb + SM_X + invA + (uint32_t)(DMAX - 1 - d) * 144u;
        const uint32_t bBase = sb + SM_K + (uint32_t)s * TAPB + invB;

        #pragma unroll
        for (int kc = 0; kc < 4; kc++) {
            uint32_t a0, a1, a2, a3, a4, a5, a6, a7;
            LDSM4(a0, a1, a2, a3, aBase + kc * 32);
            LDSM4(a4, a5, a6, a7, aBase + 2304 + kc * 32);
            #pragma unroll
            for (int nfp = 0; nfp < 4; nfp++) {
                uint32_t b0, b1, b2, b3;
                LDSM4(b0, b1, b2, b3, bBase + nfp * 2304 + kc * 32);
                mma_f16(acc[2 * nfp],         a0, a1, a2, a3, b0, b1);
                mma_f16(acc[2 * nfp + 1],     a0, a1, a2, a3, b2, b3);
                mma_f16(acc[8 + 2 * nfp],     a4, a5, a6, a7, b0, b1);
                mma_f16(acc[8 + 2 * nfp + 1], a4, a5, a6, a7, b2, b3);
            }
        }

        if (lane == 0) MBAR_ARRIVE(barE + s * 8);
        if (tid == 0 && d + NSTG < DMAX) {
            MBAR_WAIT(barE + s * 8, par);
            MBAR_EXPECT_TX(barF + s * 8, TAPB);
            bulk_g2s(sb + SM_K + s * TAPB, g_K + (size_t)(d + NSTG) * TAPH, TAPB,
                     barF + s * 8);
        }
    }

    const int r0 = t0 + wid * 32 + gid;
    #pragma unroll
    for (int nf = 0; nf < 8; nf++) {
        int col = nf * 8 + 2 * tig;
        *(float2*)(y + ((size_t)b * SEQ + r0) * DIN + col) =
            make_float2(acc[nf][0], acc[nf][1]);
        *(float2*)(y + ((size_t)b * SEQ + r0 + 8) * DIN + col) =
            make_float2(acc[nf][2], acc[nf][3]);
        *(float2*)(y + ((size_t)b * SEQ + r0 + 16) * DIN + col) =
            make_float2(acc[8 + nf][0], acc[8 + nf][1]);
        *(float2*)(y + ((size_t)b * SEQ + r0 + 24) * DIN + col) =
            make_float2(acc[8 + nf][2], acc[8 + nf][3]);
    }
}

// ---------------------------------------------------------------------------
extern "C" void kernel_launch(void* const* d_in, const int* in_sizes, int n_in,
                              void* d_out, int out_size)
{
    const float* x  = (const float*)d_in[0];
    const float* A  = (const float*)d_in[1];
    const float* Bm = (const float*)d_in[2];
    const float* Cm = (const float*)d_in[3];
    const float* Dm = (const float*)d_in[4];
    float* y = (float*)d_out;

    float* s = nullptr;
    cudaGetSymbolAddress((void**)&s, g_scratch);
    float* W = s + OFF_W;
    float* V = s + OFF_V;

    cudaFuncSetAttribute(conv_tc, cudaFuncAttributeMaxDynamicSharedMemorySize, SM_TOTAL);

    // seed W row-block 0 <- C ; V col-block 0 <- B
    cudaMemcpyAsync(W, Cm, (size_t)64 * NST * sizeof(float), cudaMemcpyDeviceToDevice);
    cudaMemcpy2DAsync(V, VW * sizeof(float), Bm, 64 * sizeof(float),
                      64 * sizeof(float), NST, cudaMemcpyDeviceToDevice);

    // whole stage 1 in one persistent launch
    stage1<<<NCTA, 256>>>(A, Dm);

    // tensor-core convolution (TM=256, warp tile 32t x 64o, 104 taps)
    conv_tc<<<dim3(SEQ / TM, BATCH), 256, SM_TOTAL>>>(x, y);
}